// round 10
// baseline (speedup 1.0000x reference)
#include <cuda_runtime.h>
#include <math.h>

#define NBATCH 256
#define NH 128
#define NB 37
#define TSTEPS 12

// ---------------- scratch (device globals; no allocation) ----------------
static __device__ float g_p1[(size_t)NBATCH * 30 * 90 * 64];   // 177 MB
static __device__ float g_p2[(size_t)NBATCH * 15 * 45 * 128];  //  88 MB
static __device__ float g_p3[(size_t)NBATCH * 8 * 23 * 128];   //  24 MB
static __device__ float g_p4[(size_t)NBATCH * 4 * 12 * 64];    //   3 MB

// ---------------- packed fp32x2 FMA (sm_100+) ----------------
__device__ __forceinline__ float2 ffma2(float2 a, float2 b, float2 c)
{
    float2 d;
    asm("fma.rn.f32x2 %0, %1, %2, %3;"
        : "=l"(reinterpret_cast<unsigned long long&>(d))
        : "l"(reinterpret_cast<unsigned long long&>(a)),
          "l"(reinterpret_cast<unsigned long long&>(b)),
          "l"(reinterpret_cast<unsigned long long&>(c)));
    return d;
}

// ---------------- fused conv3x3 + bias + BN + leakyrelu + maxpool2x2 ----------------
// Batch-PAIRED (2 batches/block, float2 smem, packed fma.rn.f32x2), ci-CHUNKED.
// Smem layout is [ci][r][col] (padded, 16B-aligned) so each (ci,r) row is read
// with broadcast LDS.128: 24 loads/ci instead of 48 -> FFMA2 issue density ~73%.
// Block: COUT threads (one per output channel), TW pooled cols of one pooled row.
template <int HIN, int WIN, int CIN, int COUT, int HOUT, int WOUT, int TW, int CHUNK>
__device__ __forceinline__ void conv_block_impl(
    const float* __restrict__ in, const float* __restrict__ w,
    const float* __restrict__ cb, const float* __restrict__ gg,
    const float* __restrict__ bb, const float* __restrict__ mm,
    const float* __restrict__ mv, float* __restrict__ out)
{
    constexpr int TC = 2 * TW + 2;
    constexpr int RSTRIDE = 4 * TC + 2;      // float2 units; keeps 16B alignment per ci
    __shared__ __align__(16) float2 sIn[CHUNK * RSTRIDE];

    const int c   = threadIdx.x;
    const int pw0 = blockIdx.x * TW;
    const int ph  = blockIdx.y;
    const int b0  = blockIdx.z * 2;          // batch pair

    const float scale = gg[c] * rsqrtf(mv[c] + 1e-5f);
    const float bias  = (cb[c] - mm[c]) * scale + bb[c];

    const int y0 = 2 * ph - 1;
    const int x0 = 2 * pw0 - 1;
    const float* inA = in + (size_t)(b0 + 0) * HIN * WIN * CIN;
    const float* inB = in + (size_t)(b0 + 1) * HIN * WIN * CIN;

    float2 acc[2][2 * TW];
#pragma unroll
    for (int i = 0; i < 2; i++)
#pragma unroll
        for (int jx = 0; jx < 2 * TW; jx++) acc[i][jx] = make_float2(0.f, 0.f);

    for (int c0 = 0; c0 < CIN; c0 += CHUNK) {
        __syncthreads();   // previous chunk fully consumed

        // cooperative tile load (ci innermost -> coalesced gmem), SAME zero pad
        for (int idx = threadIdx.x; idx < 4 * TC * CHUNK; idx += COUT) {
            int ci   = idx % CHUNK;
            int rest = idx / CHUNK;
            int col  = rest % TC;
            int r    = rest / TC;
            int y = y0 + r, x = x0 + col;
            float a = 0.f, b = 0.f;
            if (y >= 0 && y < HIN && x >= 0 && x < WIN) {
                size_t off = ((size_t)y * WIN + x) * CIN + c0 + ci;
                a = inA[off];
                b = inB[off];
            }
            sIn[ci * RSTRIDE + r * TC + col] = make_float2(a, b);
        }
        __syncthreads();

        for (int ci = 0; ci < CHUNK; ci++) {
            float2 w2[9];
#pragma unroll
            for (int tp = 0; tp < 9; tp++) {
                float wv = w[((size_t)tp * CIN + c0 + ci) * COUT + c];
                w2[tp] = make_float2(wv, wv);
            }
            // walk the 4 input rows once; each row feeds every (cy,dy=r-cy) tap
#pragma unroll
            for (int r = 0; r < 4; r++) {
                float2 rowv[TC];
                const float4* rp = (const float4*)(sIn + ci * RSTRIDE + r * TC);
#pragma unroll
                for (int q = 0; q < TC / 2; q++) {
                    float4 t = rp[q];            // broadcast LDS.128
                    rowv[2 * q]     = make_float2(t.x, t.y);
                    rowv[2 * q + 1] = make_float2(t.z, t.w);
                }
#pragma unroll
                for (int cy = 0; cy < 2; cy++) {
                    const int dy = r - cy;
                    if (dy >= 0 && dy < 3) {
#pragma unroll
                        for (int dx = 0; dx < 3; dx++) {
                            const float2 wv = w2[dy * 3 + dx];
#pragma unroll
                            for (int cx = 0; cx < 2 * TW; cx++)
                                acc[cy][cx] = ffma2(rowv[cx + dx], wv, acc[cy][cx]);
                        }
                    }
                }
            }
        }
    }

    // epilogue: BN affine + leaky relu + 2x2 SAME maxpool, both batches
#pragma unroll
    for (int pl = 0; pl < TW; pl++) {
        int pw = pw0 + pl;
        if (pw < WOUT) {
            float mA = -1e30f, mB = -1e30f;
#pragma unroll
            for (int cy = 0; cy < 2; cy++) {
                if (2 * ph + cy < HIN) {
#pragma unroll
                    for (int px = 0; px < 2; px++) {
                        int cx = 2 * pl + px;
                        if (2 * pw0 + cx < WIN) {
                            float rA = fmaf(acc[cy][cx].x, scale, bias);
                            float rB = fmaf(acc[cy][cx].y, scale, bias);
                            rA = (rA < 0.f) ? 0.01f * rA : rA;
                            rB = (rB < 0.f) ? 0.01f * rB : rB;
                            mA = fmaxf(mA, rA);
                            mB = fmaxf(mB, rB);
                        }
                    }
                }
            }
            size_t o = (((size_t)(b0 + 0) * HOUT + ph) * WOUT + pw) * COUT + c;
            out[o] = mA;
            out[o + (size_t)HOUT * WOUT * COUT] = mB;
        }
    }
}

__global__ void __launch_bounds__(64) conv_l1(
    const float* __restrict__ x, const float* __restrict__ w, const float* __restrict__ cb,
    const float* __restrict__ g, const float* __restrict__ bb, const float* __restrict__ mm,
    const float* __restrict__ mv)
{
    conv_block_impl<60, 180, 1, 64, 30, 90, 5, 1>(x, w, cb, g, bb, mm, mv, g_p1);
}

__global__ void __launch_bounds__(128) conv_l2(
    const float* __restrict__ w, const float* __restrict__ cb,
    const float* __restrict__ g, const float* __restrict__ bb, const float* __restrict__ mm,
    const float* __restrict__ mv)
{
    conv_block_impl<30, 90, 64, 128, 15, 45, 5, 32>(g_p1, w, cb, g, bb, mm, mv, g_p2);
}

__global__ void __launch_bounds__(128) conv_l3(
    const float* __restrict__ w, const float* __restrict__ cb,
    const float* __restrict__ g, const float* __restrict__ bb, const float* __restrict__ mm,
    const float* __restrict__ mv)
{
    conv_block_impl<15, 45, 128, 128, 8, 23, 5, 32>(g_p2, w, cb, g, bb, mm, mv, g_p3);
}

__global__ void __launch_bounds__(64) conv_l4(
    const float* __restrict__ w, const float* __restrict__ cb,
    const float* __restrict__ g, const float* __restrict__ bb, const float* __restrict__ mm,
    const float* __restrict__ mv)
{
    // TW=3 -> grid x=4 -> 2048 blocks (was 1536): lifts grid-limited occupancy
    conv_block_impl<8, 23, 128, 64, 4, 12, 3, 32>(g_p3, w, cb, g, bb, mm, mv, g_p4);
}

// ---------------- fully fused LSTM (2 layers x 12 steps) + projection ----------------
#define K0 384
#define K1 256

template <int K>
__device__ __forceinline__ void lstm_gates(
    const float* __restrict__ s, const float* __restrict__ W,
    const float* __restrict__ bias, int j, float2 a[4][2])
{
#pragma unroll
    for (int g = 0; g < 4; g++) {
        float bv = bias[g * NH + j];
        a[g][0] = make_float2(bv, bv);
        a[g][1] = make_float2(bv, bv);
    }
    const float4* s4 = (const float4*)s;
#pragma unroll 4
    for (int k = 0; k < K; k++) {
        float4 xv = s4[k];
        float2 xlo = make_float2(xv.x, xv.y);
        float2 xhi = make_float2(xv.z, xv.w);
        const float* Wr = W + (size_t)k * (4 * NH);
#pragma unroll
        for (int g = 0; g < 4; g++) {
            float wv = Wr[g * NH + j];
            float2 w2 = make_float2(wv, wv);
            a[g][0] = ffma2(xlo, w2, a[g][0]);
            a[g][1] = ffma2(xhi, w2, a[g][1]);
        }
    }
}

__device__ __forceinline__ float sigm(float x) { return 1.f / (1.f + expf(-x)); }

__global__ void __launch_bounds__(128) lstm_all_kernel(
    const float* __restrict__ lW0, const float* __restrict__ lb0,
    const float* __restrict__ lW1, const float* __restrict__ lb1,
    const float* __restrict__ Wout, const float* __restrict__ bout,
    float* __restrict__ out)
{
    __shared__ float s0[K0 * 4];   // [xt(256) | h0(128)] x 4 batches, layout [k][bb]
    __shared__ float s1[K1 * 4];   // [h0(128) | h1(128)] x 4 batches

    const int tid = threadIdx.x;
    const int j   = tid;           // hidden unit
    const int b0  = blockIdx.x * 4;

    float c0[4], c1[4];
#pragma unroll
    for (int bb = 0; bb < 4; bb++) { c0[bb] = 0.f; c1[bb] = 0.f; }

    for (int idx = tid; idx < 128 * 4; idx += 128) {
        s0[(256 + idx / 4) * 4 + (idx & 3)] = 0.f;
        s1[idx] = 0.f;
        s1[128 * 4 + idx] = 0.f;
    }

    for (int t = 0; t < TSTEPS; t++) {
        for (int idx = tid; idx < 4 * 256; idx += 128) {
            int bb = idx >> 8, k = idx & 255;
            int fh = k >> 6, cc = k & 63;
            s0[k * 4 + bb] = g_p4[(((size_t)(b0 + bb) * 4 + fh) * TSTEPS + t) * 64 + cc];
        }
        __syncthreads();

        float2 a0[4][2];
        lstm_gates<K0>(s0, lW0, lb0, j, a0);
        __syncthreads();

        {
            float ai[4] = {a0[0][0].x, a0[0][0].y, a0[0][1].x, a0[0][1].y};
            float aj[4] = {a0[1][0].x, a0[1][0].y, a0[1][1].x, a0[1][1].y};
            float af[4] = {a0[2][0].x, a0[2][0].y, a0[2][1].x, a0[2][1].y};
            float ao[4] = {a0[3][0].x, a0[3][0].y, a0[3][1].x, a0[3][1].y};
#pragma unroll
            for (int bb = 0; bb < 4; bb++) {
                float c = c0[bb] * sigm(af[bb] + 1.f) + sigm(ai[bb]) * tanhf(aj[bb]);
                c0[bb] = c;
                float h = tanhf(c) * sigm(ao[bb]);
                s0[(256 + j) * 4 + bb] = h;
                s1[j * 4 + bb] = h;
            }
        }
        __syncthreads();

        float2 a1[4][2];
        lstm_gates<K1>(s1, lW1, lb1, j, a1);
        __syncthreads();

        {
            float ai[4] = {a1[0][0].x, a1[0][0].y, a1[0][1].x, a1[0][1].y};
            float aj[4] = {a1[1][0].x, a1[1][0].y, a1[1][1].x, a1[1][1].y};
            float af[4] = {a1[2][0].x, a1[2][0].y, a1[2][1].x, a1[2][1].y};
            float ao[4] = {a1[3][0].x, a1[3][0].y, a1[3][1].x, a1[3][1].y};
#pragma unroll
            for (int bb = 0; bb < 4; bb++) {
                float c = c1[bb] * sigm(af[bb] + 1.f) + sigm(ai[bb]) * tanhf(aj[bb]);
                c1[bb] = c;
                s1[(128 + j) * 4 + bb] = tanhf(c) * sigm(ao[bb]);
            }
        }
        __syncthreads();

        for (int idx = tid; idx < 4 * NB; idx += 128) {
            int bb = idx / NB, nb = idx % NB;
            float acc = bout[nb];
#pragma unroll 8
            for (int k = 0; k < NH; k++)
                acc = fmaf(s1[(128 + k) * 4 + bb], Wout[k * NB + nb], acc);
            out[((size_t)t * NBATCH + (b0 + bb)) * NB + nb] = acc;
        }
    }
}

// ---------------- launch ----------------
extern "C" void kernel_launch(void* const* d_in, const int* in_sizes, int n_in,
                              void* d_out, int out_size)
{
    (void)in_sizes; (void)n_in; (void)out_size;
    const float* x = (const float*)d_in[0];
#define LW(i, k) ((const float*)d_in[1 + 6 * (i) + (k)])
    const float* lW0  = (const float*)d_in[25];
    const float* lb0  = (const float*)d_in[26];
    const float* lW1  = (const float*)d_in[27];
    const float* lb1  = (const float*)d_in[28];
    const float* Wout = (const float*)d_in[29];
    const float* bout = (const float*)d_in[30];
    float* out = (float*)d_out;

    conv_l1<<<dim3(18, 30, NBATCH / 2), 64>>>(x, LW(0, 0), LW(0, 1), LW(0, 2), LW(0, 3), LW(0, 4), LW(0, 5));
    conv_l2<<<dim3(9, 15, NBATCH / 2), 128>>>(LW(1, 0), LW(1, 1), LW(1, 2), LW(1, 3), LW(1, 4), LW(1, 5));
    conv_l3<<<dim3(5, 8, NBATCH / 2), 128>>>(LW(2, 0), LW(2, 1), LW(2, 2), LW(2, 3), LW(2, 4), LW(2, 5));
    conv_l4<<<dim3(4, 4, NBATCH / 2), 64>>>(LW(3, 0), LW(3, 1), LW(3, 2), LW(3, 3), LW(3, 4), LW(3, 5));

    lstm_all_kernel<<<NBATCH / 4, 128>>>(lW0, lb0, lW1, lb1, Wout, bout, out);
#undef LW
}

// round 11
// speedup vs baseline: 1.0597x; 1.0597x over previous
#include <cuda_runtime.h>
#include <math.h>

#define NBATCH 256
#define NH 128
#define NB 37
#define TSTEPS 12

// ---------------- scratch (device globals; no allocation) ----------------
static __device__ float g_p1[(size_t)NBATCH * 30 * 90 * 64];   // 177 MB
static __device__ float g_p2[(size_t)NBATCH * 15 * 45 * 128];  //  88 MB
static __device__ float g_p3[(size_t)NBATCH * 8 * 23 * 128];   //  24 MB
static __device__ float g_p4[(size_t)NBATCH * 4 * 12 * 64];    //   3 MB

// ---------------- packed fp32x2 FMA (sm_100+) ----------------
__device__ __forceinline__ float2 ffma2(float2 a, float2 b, float2 c)
{
    float2 d;
    asm("fma.rn.f32x2 %0, %1, %2, %3;"
        : "=l"(reinterpret_cast<unsigned long long&>(d))
        : "l"(reinterpret_cast<unsigned long long&>(a)),
          "l"(reinterpret_cast<unsigned long long&>(b)),
          "l"(reinterpret_cast<unsigned long long&>(c)));
    return d;
}

// ---------------- fused conv3x3 + bias + BN + leakyrelu + maxpool2x2 ----------------
// Batch-PAIRED (2 batches/block, float2 smem, packed fma.rn.f32x2), ci-CHUNKED,
// and ci-PAIR-UNROLLED: smem layout [pos][ci] (R8's conflict-free layout); one
// broadcast LDS.128 at [(pos)*CHUNK + ci] yields BOTH ci and ci+1 float2 values,
// halving shared loads; the 18 weight LDGs per pair issue back-to-back (MLP).
// Block: COUT threads (one per output channel), TW pooled cols of one pooled row.
template <int HIN, int WIN, int CIN, int COUT, int HOUT, int WOUT, int TW, int CHUNK>
__device__ __forceinline__ void conv_block_impl(
    const float* __restrict__ in, const float* __restrict__ w,
    const float* __restrict__ cb, const float* __restrict__ gg,
    const float* __restrict__ bb, const float* __restrict__ mm,
    const float* __restrict__ mv, float* __restrict__ out)
{
    constexpr int TC = 2 * TW + 2;
    __shared__ __align__(16) float2 sIn[4 * TC * CHUNK];

    const int c   = threadIdx.x;
    const int pw0 = blockIdx.x * TW;
    const int ph  = blockIdx.y;
    const int b0  = blockIdx.z * 2;          // batch pair

    const float scale = gg[c] * rsqrtf(mv[c] + 1e-5f);
    const float bias  = (cb[c] - mm[c]) * scale + bb[c];

    const int y0 = 2 * ph - 1;
    const int x0 = 2 * pw0 - 1;
    const float* inA = in + (size_t)(b0 + 0) * HIN * WIN * CIN;
    const float* inB = in + (size_t)(b0 + 1) * HIN * WIN * CIN;

    float2 acc[2][2 * TW];
#pragma unroll
    for (int i = 0; i < 2; i++)
#pragma unroll
        for (int jx = 0; jx < 2 * TW; jx++) acc[i][jx] = make_float2(0.f, 0.f);

    for (int c0 = 0; c0 < CIN; c0 += CHUNK) {
        __syncthreads();   // previous chunk fully consumed

        // cooperative tile load (ci innermost -> coalesced gmem, conflict-free STS)
        for (int idx = threadIdx.x; idx < 4 * TC * CHUNK; idx += COUT) {
            int ci   = (CHUNK == 1) ? 0 : (idx % CHUNK);
            int rest = (CHUNK == 1) ? idx : (idx / CHUNK);
            int col  = rest % TC;
            int r    = rest / TC;
            int y = y0 + r, x = x0 + col;
            float a = 0.f, b = 0.f;
            if (y >= 0 && y < HIN && x >= 0 && x < WIN) {
                size_t off = ((size_t)y * WIN + x) * CIN + c0 + ci;
                a = inA[off];
                b = inB[off];
            }
            sIn[idx] = make_float2(a, b);
        }
        __syncthreads();

        if (CHUNK == 1) {
            // scalar path (conv1: CIN=1)
            float2 w2[9];
#pragma unroll
            for (int tp = 0; tp < 9; tp++) {
                float wv = w[((size_t)tp * CIN + c0) * COUT + c];
                w2[tp] = make_float2(wv, wv);
            }
#pragma unroll
            for (int r = 0; r < 4; r++) {
                float2 rowv[TC];
#pragma unroll
                for (int col = 0; col < TC; col++) rowv[col] = sIn[r * TC + col];
#pragma unroll
                for (int cy = 0; cy < 2; cy++) {
                    const int dy = r - cy;
                    if (dy >= 0 && dy < 3) {
#pragma unroll
                        for (int dx = 0; dx < 3; dx++) {
                            const float2 wv = w2[dy * 3 + dx];
#pragma unroll
                            for (int cx = 0; cx < 2 * TW; cx++)
                                acc[cy][cx] = ffma2(rowv[cx + dx], wv, acc[cy][cx]);
                        }
                    }
                }
            }
        } else {
            // ci-pair path: 18 batched weight LDGs, paired LDS.128 row reads
            for (int ci = 0; ci < CHUNK; ci += 2) {
                float2 wa[9], wb[9];
#pragma unroll
                for (int tp = 0; tp < 9; tp++) {
                    const float* wr = w + ((size_t)tp * CIN + c0 + ci) * COUT + c;
                    float va = wr[0];
                    float vb = wr[COUT];
                    wa[tp] = make_float2(va, va);
                    wb[tp] = make_float2(vb, vb);
                }
#pragma unroll
                for (int r = 0; r < 4; r++) {
                    float2 ra[TC], rb[TC];
#pragma unroll
                    for (int col = 0; col < TC; col++) {
                        float4 t = *(const float4*)(sIn + (r * TC + col) * CHUNK + ci);
                        ra[col] = make_float2(t.x, t.y);
                        rb[col] = make_float2(t.z, t.w);
                    }
#pragma unroll
                    for (int cy = 0; cy < 2; cy++) {
                        const int dy = r - cy;
                        if (dy >= 0 && dy < 3) {
#pragma unroll
                            for (int dx = 0; dx < 3; dx++) {
                                const float2 wva = wa[dy * 3 + dx];
                                const float2 wvb = wb[dy * 3 + dx];
#pragma unroll
                                for (int cx = 0; cx < 2 * TW; cx++) {
                                    acc[cy][cx] = ffma2(ra[cx + dx], wva, acc[cy][cx]);
                                    acc[cy][cx] = ffma2(rb[cx + dx], wvb, acc[cy][cx]);
                                }
                            }
                        }
                    }
                }
            }
        }
    }

    // epilogue: BN affine + leaky relu + 2x2 SAME maxpool, both batches
#pragma unroll
    for (int pl = 0; pl < TW; pl++) {
        int pw = pw0 + pl;
        if (pw < WOUT) {
            float mA = -1e30f, mB = -1e30f;
#pragma unroll
            for (int cy = 0; cy < 2; cy++) {
                if (2 * ph + cy < HIN) {
#pragma unroll
                    for (int px = 0; px < 2; px++) {
                        int cx = 2 * pl + px;
                        if (2 * pw0 + cx < WIN) {
                            float rA = fmaf(acc[cy][cx].x, scale, bias);
                            float rB = fmaf(acc[cy][cx].y, scale, bias);
                            rA = (rA < 0.f) ? 0.01f * rA : rA;
                            rB = (rB < 0.f) ? 0.01f * rB : rB;
                            mA = fmaxf(mA, rA);
                            mB = fmaxf(mB, rB);
                        }
                    }
                }
            }
            size_t o = (((size_t)(b0 + 0) * HOUT + ph) * WOUT + pw) * COUT + c;
            out[o] = mA;
            out[o + (size_t)HOUT * WOUT * COUT] = mB;
        }
    }
}

__global__ void __launch_bounds__(64) conv_l1(
    const float* __restrict__ x, const float* __restrict__ w, const float* __restrict__ cb,
    const float* __restrict__ g, const float* __restrict__ bb, const float* __restrict__ mm,
    const float* __restrict__ mv)
{
    conv_block_impl<60, 180, 1, 64, 30, 90, 5, 1>(x, w, cb, g, bb, mm, mv, g_p1);
}

__global__ void __launch_bounds__(128) conv_l2(
    const float* __restrict__ w, const float* __restrict__ cb,
    const float* __restrict__ g, const float* __restrict__ bb, const float* __restrict__ mm,
    const float* __restrict__ mv)
{
    conv_block_impl<30, 90, 64, 128, 15, 45, 5, 32>(g_p1, w, cb, g, bb, mm, mv, g_p2);
}

__global__ void __launch_bounds__(128) conv_l3(
    const float* __restrict__ w, const float* __restrict__ cb,
    const float* __restrict__ g, const float* __restrict__ bb, const float* __restrict__ mm,
    const float* __restrict__ mv)
{
    conv_block_impl<15, 45, 128, 128, 8, 23, 5, 32>(g_p2, w, cb, g, bb, mm, mv, g_p3);
}

__global__ void __launch_bounds__(64) conv_l4(
    const float* __restrict__ w, const float* __restrict__ cb,
    const float* __restrict__ g, const float* __restrict__ bb, const float* __restrict__ mm,
    const float* __restrict__ mv)
{
    conv_block_impl<8, 23, 128, 64, 4, 12, 3, 32>(g_p3, w, cb, g, bb, mm, mv, g_p4);
}

// ---------------- fully fused LSTM (2 layers x 12 steps) + projection ----------------
#define K0 384
#define K1 256

template <int K>
__device__ __forceinline__ void lstm_gates(
    const float* __restrict__ s, const float* __restrict__ W,
    const float* __restrict__ bias, int j, float2 a[4][2])
{
#pragma unroll
    for (int g = 0; g < 4; g++) {
        float bv = bias[g * NH + j];
        a[g][0] = make_float2(bv, bv);
        a[g][1] = make_float2(bv, bv);
    }
    const float4* s4 = (const float4*)s;
#pragma unroll 4
    for (int k = 0; k < K; k++) {
        float4 xv = s4[k];
        float2 xlo = make_float2(xv.x, xv.y);
        float2 xhi = make_float2(xv.z, xv.w);
        const float* Wr = W + (size_t)k * (4 * NH);
#pragma unroll
        for (int g = 0; g < 4; g++) {
            float wv = Wr[g * NH + j];
            float2 w2 = make_float2(wv, wv);
            a[g][0] = ffma2(xlo, w2, a[g][0]);
            a[g][1] = ffma2(xhi, w2, a[g][1]);
        }
    }
}

__device__ __forceinline__ float sigm(float x) { return 1.f / (1.f + expf(-x)); }

__global__ void __launch_bounds__(128) lstm_all_kernel(
    const float* __restrict__ lW0, const float* __restrict__ lb0,
    const float* __restrict__ lW1, const float* __restrict__ lb1,
    const float* __restrict__ Wout, const float* __restrict__ bout,
    float* __restrict__ out)
{
    __shared__ float s0[K0 * 4];   // [xt(256) | h0(128)] x 4 batches, layout [k][bb]
    __shared__ float s1[K1 * 4];   // [h0(128) | h1(128)] x 4 batches

    const int tid = threadIdx.x;
    const int j   = tid;           // hidden unit
    const int b0  = blockIdx.x * 4;

    float c0[4], c1[4];
#pragma unroll
    for (int bb = 0; bb < 4; bb++) { c0[bb] = 0.f; c1[bb] = 0.f; }

    for (int idx = tid; idx < 128 * 4; idx += 128) {
        s0[(256 + idx / 4) * 4 + (idx & 3)] = 0.f;
        s1[idx] = 0.f;
        s1[128 * 4 + idx] = 0.f;
    }

    for (int t = 0; t < TSTEPS; t++) {
        for (int idx = tid; idx < 4 * 256; idx += 128) {
            int bb = idx >> 8, k = idx & 255;
            int fh = k >> 6, cc = k & 63;
            s0[k * 4 + bb] = g_p4[(((size_t)(b0 + bb) * 4 + fh) * TSTEPS + t) * 64 + cc];
        }
        __syncthreads();

        float2 a0[4][2];
        lstm_gates<K0>(s0, lW0, lb0, j, a0);
        __syncthreads();

        {
            float ai[4] = {a0[0][0].x, a0[0][0].y, a0[0][1].x, a0[0][1].y};
            float aj[4] = {a0[1][0].x, a0[1][0].y, a0[1][1].x, a0[1][1].y};
            float af[4] = {a0[2][0].x, a0[2][0].y, a0[2][1].x, a0[2][1].y};
            float ao[4] = {a0[3][0].x, a0[3][0].y, a0[3][1].x, a0[3][1].y};
#pragma unroll
            for (int bb = 0; bb < 4; bb++) {
                float c = c0[bb] * sigm(af[bb] + 1.f) + sigm(ai[bb]) * tanhf(aj[bb]);
                c0[bb] = c;
                float h = tanhf(c) * sigm(ao[bb]);
                s0[(256 + j) * 4 + bb] = h;
                s1[j * 4 + bb] = h;
            }
        }
        __syncthreads();

        float2 a1[4][2];
        lstm_gates<K1>(s1, lW1, lb1, j, a1);
        __syncthreads();

        {
            float ai[4] = {a1[0][0].x, a1[0][0].y, a1[0][1].x, a1[0][1].y};
            float aj[4] = {a1[1][0].x, a1[1][0].y, a1[1][1].x, a1[1][1].y};
            float af[4] = {a1[2][0].x, a1[2][0].y, a1[2][1].x, a1[2][1].y};
            float ao[4] = {a1[3][0].x, a1[3][0].y, a1[3][1].x, a1[3][1].y};
#pragma unroll
            for (int bb = 0; bb < 4; bb++) {
                float c = c1[bb] * sigm(af[bb] + 1.f) + sigm(ai[bb]) * tanhf(aj[bb]);
                c1[bb] = c;
                s1[(128 + j) * 4 + bb] = tanhf(c) * sigm(ao[bb]);
            }
        }
        __syncthreads();

        for (int idx = tid; idx < 4 * NB; idx += 128) {
            int bb = idx / NB, nb = idx % NB;
            float acc = bout[nb];
#pragma unroll 8
            for (int k = 0; k < NH; k++)
                acc = fmaf(s1[(128 + k) * 4 + bb], Wout[k * NB + nb], acc);
            out[((size_t)t * NBATCH + (b0 + bb)) * NB + nb] = acc;
        }
    }
}

// ---------------- launch ----------------
extern "C" void kernel_launch(void* const* d_in, const int* in_sizes, int n_in,
                              void* d_out, int out_size)
{
    (void)in_sizes; (void)n_in; (void)out_size;
    const float* x = (const float*)d_in[0];
#define LW(i, k) ((const float*)d_in[1 + 6 * (i) + (k)])
    const float* lW0  = (const float*)d_in[25];
    const float* lb0  = (const float*)d_in[26];
    const float* lW1  = (const float*)d_in[27];
    const float* lb1  = (const float*)d_in[28];
    const float* Wout = (const float*)d_in[29];
    const float* bout = (const float*)d_in[30];
    float* out = (float*)d_out;

    conv_l1<<<dim3(18, 30, NBATCH / 2), 64>>>(x, LW(0, 0), LW(0, 1), LW(0, 2), LW(0, 3), LW(0, 4), LW(0, 5));
    conv_l2<<<dim3(9, 15, NBATCH / 2), 128>>>(LW(1, 0), LW(1, 1), LW(1, 2), LW(1, 3), LW(1, 4), LW(1, 5));
    conv_l3<<<dim3(5, 8, NBATCH / 2), 128>>>(LW(2, 0), LW(2, 1), LW(2, 2), LW(2, 3), LW(2, 4), LW(2, 5));
    conv_l4<<<dim3(4, 4, NBATCH / 2), 64>>>(LW(3, 0), LW(3, 1), LW(3, 2), LW(3, 3), LW(3, 4), LW(3, 5));

    lstm_all_kernel<<<NBATCH / 4, 128>>>(lW0, lb0, lW1, lb1, Wout, bout, out);
#undef LW
}